// round 1
// baseline (speedup 1.0000x reference)
#include <cuda_runtime.h>
#include <cstdint>

#define NSEQ 128
#define TB   4096
#define FIN  208
#define HGRU 131
#define HP   132      // padded hidden (even, 16B-aligned rows)
#define G3   393      // 3*H
#define DMLP 255
#define DOUT 17

// ---- scratch (no allocations allowed; __device__ globals) ----
__device__ float g_wpad[G3 * HP];     // W_hh packed [393][132], col 131 zero
__device__ float g_gi[NSEQ * G3];     // input-gate preactivations for lane 4095
__device__ float g_x[NSEQ * HGRU];    // GRU outputs
__device__ float g_a[NSEQ * DMLP];
__device__ float g_b[NSEQ * DMLP];

// ---- pack W_hh into padded rows ----
__global__ void pack_whh_kernel(const float* __restrict__ W) {
    int idx = blockIdx.x * blockDim.x + threadIdx.x;
    if (idx < G3 * HP) {
        int j = idx / HP, k = idx - j * HP;
        g_wpad[idx] = (k < HGRU) ? W[j * HGRU + k] : 0.f;
    }
}

// ---- generic fused FC: Y[r,c] = act( X[r,:] . W[c,:] + B[c] ) ----
// block = 512 threads = 16 rows x 32 cols; smem-tiled, odd pitch (bank-conflict-free)
__global__ __launch_bounds__(512) void fc_kernel(
    const float* __restrict__ X, int xstride,
    const float* __restrict__ W, const float* __restrict__ B,
    float* __restrict__ Y, int Din, int Dout, int relu)
{
    __shared__ float xs[16 * 255];
    __shared__ float ws[32 * 255];
    const int pd = Din | 1;
    const int tid = threadIdx.x;
    const int rowbase = blockIdx.y * 16;
    const int colbase = blockIdx.x * 32;

    for (int idx = tid; idx < 16 * Din; idx += 512) {
        int r = idx / Din, k = idx - r * Din;
        xs[r * pd + k] = X[(size_t)(rowbase + r) * xstride + k];
    }
    for (int idx = tid; idx < 32 * Din; idx += 512) {
        int c = idx / Din, k = idx - c * Din;
        int col = colbase + c;
        ws[c * pd + k] = (col < Dout) ? W[(size_t)col * Din + k] : 0.f;
    }
    __syncthreads();

    const int c = tid & 31, r = tid >> 5;
    const float* xr = xs + r * pd;
    const float* wr = ws + c * pd;
    float a0 = 0.f, a1 = 0.f, a2 = 0.f, a3 = 0.f;
    int k = 0;
    for (; k + 4 <= Din; k += 4) {
        a0 = fmaf(xr[k],     wr[k],     a0);
        a1 = fmaf(xr[k + 1], wr[k + 1], a1);
        a2 = fmaf(xr[k + 2], wr[k + 2], a2);
        a3 = fmaf(xr[k + 3], wr[k + 3], a3);
    }
    for (; k < Din; k++) a0 = fmaf(xr[k], wr[k], a0);

    int col = colbase + c;
    if (col < Dout) {
        float acc = ((a0 + a1) + (a2 + a3)) + B[col];
        if (relu) acc = fmaxf(acc, 0.f);
        Y[(rowbase + r) * Dout + col] = acc;
    }
}

// ---- GRU recurrence: single CTA, W_hh in registers, packed f32x2 FMA ----
__device__ __forceinline__ float fast_sigmoid(float x) {
    return 1.f / (1.f + __expf(-x));
}
__device__ __forceinline__ float fast_tanh(float x) {
    float e = __expf(-2.f * x);
    return (1.f - e) / (1.f + e);
}

__global__ __launch_bounds__(416, 1) void gru_kernel(const float* __restrict__ b_hh)
{
    __shared__ __align__(16) float h_sh[HP];
    __shared__ float gh_sh[G3];
    __shared__ float gi_sh[G3];
    const int j = threadIdx.x;

    // load W_hh row j into registers as 66 packed fp32 pairs
    unsigned long long w2[66];
    float bj = 0.f;
    if (j < G3) {
        const unsigned long long* wr =
            reinterpret_cast<const unsigned long long*>(g_wpad + j * HP);
#pragma unroll
        for (int i = 0; i < 66; i++) w2[i] = wr[i];
        bj = b_hh[j];
    }
    if (j < HP) h_sh[j] = 0.f;

    uint32_t h_addr;
    asm("{ .reg .u64 t; cvta.to.shared.u64 t, %1; cvt.u32.u64 %0, t; }"
        : "=r"(h_addr) : "l"(h_sh));

    float gi_v = (j < G3) ? g_gi[j] : 0.f;   // step 0 prefetch
    __syncthreads();

    for (int n = 0; n < NSEQ; n++) {
        float gi_cur = gi_v;
        if (j < G3 && n + 1 < NSEQ) gi_v = __ldg(g_gi + (n + 1) * G3 + j);

        if (j < G3) {
            unsigned long long acc0, acc1 = 0ULL;
            asm("mov.b64 %0, {%1, %2};" : "=l"(acc0) : "f"(bj), "f"(0.f));
#pragma unroll
            for (int i = 0; i < 33; i++) {
                unsigned long long h0, h1;
                asm volatile("ld.shared.v2.u64 {%0, %1}, [%2];"
                             : "=l"(h0), "=l"(h1) : "r"(h_addr + i * 16));
                asm("fma.rn.f32x2 %0, %1, %2, %0;" : "+l"(acc0)
                    : "l"(h0), "l"(w2[2 * i]));
                asm("fma.rn.f32x2 %0, %1, %2, %0;" : "+l"(acc1)
                    : "l"(h1), "l"(w2[2 * i + 1]));
            }
            float a0, a1, a2, a3;
            asm("mov.b64 {%0, %1}, %2;" : "=f"(a0), "=f"(a1) : "l"(acc0));
            asm("mov.b64 {%0, %1}, %2;" : "=f"(a2), "=f"(a3) : "l"(acc1));
            gh_sh[j] = (a0 + a2) + (a1 + a3);
            gi_sh[j] = gi_cur;
        }
        __syncthreads();

        if (j < HGRU) {
            float ir = gi_sh[j], iz = gi_sh[j + HGRU], in_ = gi_sh[j + 2 * HGRU];
            float hr = gh_sh[j], hz = gh_sh[j + HGRU], hn = gh_sh[j + 2 * HGRU];
            float r  = fast_sigmoid(ir + hr);
            float z  = fast_sigmoid(iz + hz);
            float nn = fast_tanh(in_ + r * hn);
            float hp = h_sh[j];
            float hnew = nn + z * (hp - nn);
            h_sh[j] = hnew;
            g_x[n * HGRU + j] = hnew;
        }
        __syncthreads();
    }
}

extern "C" void kernel_launch(void* const* d_in, const int* in_sizes, int n_in,
                              void* d_out, int out_size)
{
    const float* history = (const float*)d_in[0];
    const float* W_ih = (const float*)d_in[1];
    const float* W_hh = (const float*)d_in[2];
    const float* b_ih = (const float*)d_in[3];
    const float* b_hh = (const float*)d_in[4];
    const float* W1 = (const float*)d_in[5];  const float* b1 = (const float*)d_in[6];
    const float* W2 = (const float*)d_in[7];  const float* b2 = (const float*)d_in[8];
    const float* W3 = (const float*)d_in[9];  const float* b3 = (const float*)d_in[10];
    const float* W4 = (const float*)d_in[11]; const float* b4 = (const float*)d_in[12];
    const float* W5 = (const float*)d_in[13]; const float* b5 = (const float*)d_in[14];
    const float* W6 = (const float*)d_in[15]; const float* b6 = (const float*)d_in[16];
    float* out = (float*)d_out;

    float *gi, *x, *a, *b;
    cudaGetSymbolAddress((void**)&gi, g_gi);
    cudaGetSymbolAddress((void**)&x,  g_x);
    cudaGetSymbolAddress((void**)&a,  g_a);
    cudaGetSymbolAddress((void**)&b,  g_b);

    // pack W_hh into padded rows for the register-resident recurrence
    pack_whh_kernel<<<(G3 * HP + 511) / 512, 512>>>(W_hh);

    // gi = history[:, 4095, :] @ W_ih^T + b_ih   (only last lane is observable)
    fc_kernel<<<dim3((G3 + 31) / 32, 8), 512>>>(
        history + 4095 * FIN, TB * FIN, W_ih, b_ih, gi, FIN, G3, 0);

    // sequential GRU over 128 steps (single CTA)
    gru_kernel<<<1, 416>>>(b_hh);

    // 6-layer MLP
    fc_kernel<<<dim3(8, 8), 512>>>(x, HGRU, W1, b1, a, HGRU, DMLP, 1);
    fc_kernel<<<dim3(8, 8), 512>>>(a, DMLP, W2, b2, b, DMLP, DMLP, 1);
    fc_kernel<<<dim3(8, 8), 512>>>(b, DMLP, W3, b3, a, DMLP, DMLP, 1);
    fc_kernel<<<dim3(8, 8), 512>>>(a, DMLP, W4, b4, b, DMLP, DMLP, 1);
    fc_kernel<<<dim3(8, 8), 512>>>(b, DMLP, W5, b5, a, DMLP, DMLP, 1);
    fc_kernel<<<dim3(1, 8), 512>>>(a, DMLP, W6, b6, out, DMLP, DOUT, 0);
}

// round 2
// speedup vs baseline: 1.0130x; 1.0130x over previous
#include <cuda_runtime.h>
#include <cstdint>

#define NSEQ 128
#define TB   4096
#define FIN  208
#define HGRU 131
#define HP   132      // padded hidden (even, 16B-aligned rows)
#define G3   393      // 3*H
#define DMLP 255
#define DOUT 17

#define NREGP 56      // weight pairs held in registers (112 floats)
#define NTAIL 10      // weight pairs held in smem (20 floats incl 1 pad)

typedef unsigned long long ull;

// ---- scratch (__device__ globals; zero-initialized at module load) ----
__device__ float g_wpad[G3 * HP];     // W_hh padded [393][132]
__device__ float g_gi[NSEQ * G3];     // input-gate preactivations, lane 4095
__device__ float g_x[NSEQ * HP];      // GRU outputs, pitch 132, col 131 == 0
__device__ float g_a[NSEQ * 256];     // MLP ping (pitch 256, pad col == 0)
__device__ float g_b[NSEQ * 256];     // MLP pong
__device__ float g_w1p[DMLP * HP];    // W1 padded 255x132
__device__ float g_w2p[DMLP * 256];
__device__ float g_w3p[DMLP * 256];
__device__ float g_w4p[DMLP * 256];
__device__ float g_w5p[DMLP * 256];
__device__ float g_w6p[DOUT * 256];

// ---- one prep kernel: pad all weight matrices to 16B-aligned pitches ----
__global__ void prep_kernel(const float* __restrict__ Whh,
                            const float* __restrict__ W1,
                            const float* __restrict__ W2,
                            const float* __restrict__ W3,
                            const float* __restrict__ W4,
                            const float* __restrict__ W5,
                            const float* __restrict__ W6)
{
    int idx = blockIdx.x * blockDim.x + threadIdx.x;
    const int s0 = G3 * HP;
    const int s1 = DMLP * HP;
    const int s2 = DMLP * 256;
    const int s6 = DOUT * 256;

    if (idx < s0) {
        int j = idx / HP, k = idx - j * HP;
        g_wpad[idx] = (k < HGRU) ? Whh[j * HGRU + k] : 0.f;
        return;
    }
    idx -= s0;
    if (idx < s1) {
        int j = idx / HP, k = idx - j * HP;
        g_w1p[idx] = (k < HGRU) ? W1[j * HGRU + k] : 0.f;
        return;
    }
    idx -= s1;
    if (idx < s2) {
        int j = idx >> 8, k = idx & 255;
        g_w2p[idx] = (k < DMLP) ? W2[j * DMLP + k] : 0.f;
        return;
    }
    idx -= s2;
    if (idx < s2) {
        int j = idx >> 8, k = idx & 255;
        g_w3p[idx] = (k < DMLP) ? W3[j * DMLP + k] : 0.f;
        return;
    }
    idx -= s2;
    if (idx < s2) {
        int j = idx >> 8, k = idx & 255;
        g_w4p[idx] = (k < DMLP) ? W4[j * DMLP + k] : 0.f;
        return;
    }
    idx -= s2;
    if (idx < s2) {
        int j = idx >> 8, k = idx & 255;
        g_w5p[idx] = (k < DMLP) ? W5[j * DMLP + k] : 0.f;
        return;
    }
    idx -= s2;
    if (idx < s6) {
        int j = idx >> 8, k = idx & 255;
        g_w6p[idx] = (k < DMLP) ? W6[j * DMLP + k] : 0.f;
    }
}

// ---- FC: dot-product warps. Each CTA = 2 rows; warp strides over columns;
//      32 lanes split K; X row register-resident; W read as coalesced float4.
__global__ __launch_bounds__(512) void fc2_kernel(
    const float* __restrict__ X, int xstride,      // element stride between rows
    const float* __restrict__ Wp, int wf4,         // float4s per W row
    const float* __restrict__ B,
    float* __restrict__ Y, int ystride,
    int din_f4, int dout, int relu)
{
    const int lane = threadIdx.x & 31;
    const int warp = threadIdx.x >> 5;
    const int r0 = blockIdx.x * 2;

    const bool gA = lane < din_f4;
    const bool gB = lane + 32 < din_f4;

    float4 x0a = make_float4(0.f, 0.f, 0.f, 0.f), x0b = x0a;
    float4 x1a = x0a, x1b = x0a;
    const float4* X0 = reinterpret_cast<const float4*>(X + (size_t)r0 * xstride);
    const float4* X1 = reinterpret_cast<const float4*>(X + (size_t)(r0 + 1) * xstride);
    if (gA) { x0a = X0[lane];      x1a = X1[lane]; }
    if (gB) { x0b = X0[lane + 32]; x1b = X1[lane + 32]; }

    const float4 z4 = make_float4(0.f, 0.f, 0.f, 0.f);

    for (int c = warp; c < dout; c += 16) {
        const float4* Wr = reinterpret_cast<const float4*>(Wp) + (size_t)c * wf4;
        float4 wa = gA ? Wr[lane]      : z4;
        float4 wb = gB ? Wr[lane + 32] : z4;

        float s0 = x0a.x * wa.x;
        s0 = fmaf(x0a.y, wa.y, s0); s0 = fmaf(x0a.z, wa.z, s0); s0 = fmaf(x0a.w, wa.w, s0);
        s0 = fmaf(x0b.x, wb.x, s0); s0 = fmaf(x0b.y, wb.y, s0);
        s0 = fmaf(x0b.z, wb.z, s0); s0 = fmaf(x0b.w, wb.w, s0);

        float s1 = x1a.x * wa.x;
        s1 = fmaf(x1a.y, wa.y, s1); s1 = fmaf(x1a.z, wa.z, s1); s1 = fmaf(x1a.w, wa.w, s1);
        s1 = fmaf(x1b.x, wb.x, s1); s1 = fmaf(x1b.y, wb.y, s1);
        s1 = fmaf(x1b.z, wb.z, s1); s1 = fmaf(x1b.w, wb.w, s1);

#pragma unroll
        for (int off = 16; off; off >>= 1) {
            s0 += __shfl_xor_sync(0xffffffffu, s0, off);
            s1 += __shfl_xor_sync(0xffffffffu, s1, off);
        }

        if (lane == 0) {
            float bv = B[c];
            float v0 = s0 + bv, v1 = s1 + bv;
            if (relu) { v0 = fmaxf(v0, 0.f); v1 = fmaxf(v1, 0.f); }
            Y[(size_t)r0 * ystride + c]       = v0;
            Y[(size_t)(r0 + 1) * ystride + c] = v1;
        }
    }
}

// ---- GRU recurrence: single CTA, 112 weight floats in regs + 20 in smem ----
__device__ __forceinline__ float fast_sigmoid(float x) {
    return 1.f / (1.f + __expf(-x));
}
__device__ __forceinline__ float fast_tanh(float x) {
    float e = __expf(-2.f * x);
    return (1.f - e) / (1.f + e);
}

__global__ __launch_bounds__(416, 1) void gru_kernel(const float* __restrict__ b_hh)
{
    __shared__ __align__(16) float h_sh[HP];
    __shared__ float gh_sh[G3];
    __shared__ float gi_sh[G3];
    __shared__ ull tail_w[NTAIL][416];   // transposed tail: [pair][thread]

    const int j = threadIdx.x;

    ull w2[NREGP];
    float bj = 0.f;
    if (j < G3) {
        const ull* wr = reinterpret_cast<const ull*>(g_wpad + j * HP);
#pragma unroll
        for (int i = 0; i < NREGP; i++) w2[i] = wr[i];
#pragma unroll
        for (int t = 0; t < NTAIL; t++) tail_w[t][j] = wr[NREGP + t];
        bj = b_hh[j];
    }
    if (j < HP) h_sh[j] = 0.f;

    uint32_t h_addr;
    asm("{ .reg .u64 t; cvta.to.shared.u64 t, %1; cvt.u32.u64 %0, t; }"
        : "=r"(h_addr) : "l"(h_sh));

    float gi_v = (j < G3) ? g_gi[j] : 0.f;   // step-0 prefetch
    __syncthreads();

    for (int n = 0; n < NSEQ; n++) {
        float gi_cur = gi_v;
        if (j < G3 && n + 1 < NSEQ) gi_v = __ldg(g_gi + (n + 1) * G3 + j);

        if (j < G3) {
            ull acc0, acc1 = 0ULL;
            asm("mov.b64 %0, {%1, %2};" : "=l"(acc0) : "f"(bj), "f"(0.f));
            // register part: pairs 0..55 (floats 0..111)
#pragma unroll
            for (int i = 0; i < NREGP / 2; i++) {
                ull h0, h1;
                asm volatile("ld.shared.v2.u64 {%0, %1}, [%2];"
                             : "=l"(h0), "=l"(h1) : "r"(h_addr + i * 16));
                asm("fma.rn.f32x2 %0, %1, %2, %0;" : "+l"(acc0)
                    : "l"(h0), "l"(w2[2 * i]));
                asm("fma.rn.f32x2 %0, %1, %2, %0;" : "+l"(acc1)
                    : "l"(h1), "l"(w2[2 * i + 1]));
            }
            // smem tail: pairs 56..65 (floats 112..131, last is zero pad)
#pragma unroll
            for (int t = 0; t < NTAIL / 2; t++) {
                ull h0, h1;
                asm volatile("ld.shared.v2.u64 {%0, %1}, [%2];"
                             : "=l"(h0), "=l"(h1)
                             : "r"(h_addr + (NREGP + 2 * t) * 8));
                ull tw0 = tail_w[2 * t][j];
                ull tw1 = tail_w[2 * t + 1][j];
                asm("fma.rn.f32x2 %0, %1, %2, %0;" : "+l"(acc0)
                    : "l"(h0), "l"(tw0));
                asm("fma.rn.f32x2 %0, %1, %2, %0;" : "+l"(acc1)
                    : "l"(h1), "l"(tw1));
            }
            float a0, a1, a2, a3;
            asm("mov.b64 {%0, %1}, %2;" : "=f"(a0), "=f"(a1) : "l"(acc0));
            asm("mov.b64 {%0, %1}, %2;" : "=f"(a2), "=f"(a3) : "l"(acc1));
            gh_sh[j] = (a0 + a2) + (a1 + a3);
            gi_sh[j] = gi_cur;
        }
        __syncthreads();

        if (j < HGRU) {
            float ir = gi_sh[j], iz = gi_sh[j + HGRU], in_ = gi_sh[j + 2 * HGRU];
            float hr = gh_sh[j], hz = gh_sh[j + HGRU], hn = gh_sh[j + 2 * HGRU];
            float r  = fast_sigmoid(ir + hr);
            float z  = fast_sigmoid(iz + hz);
            float nn = fast_tanh(in_ + r * hn);
            float hp = h_sh[j];
            float hnew = nn + z * (hp - nn);
            h_sh[j] = hnew;
            g_x[n * HP + j] = hnew;          // pitch 132; col 131 stays 0
        }
        __syncthreads();
    }
}

extern "C" void kernel_launch(void* const* d_in, const int* in_sizes, int n_in,
                              void* d_out, int out_size)
{
    const float* history = (const float*)d_in[0];
    const float* W_ih = (const float*)d_in[1];
    const float* W_hh = (const float*)d_in[2];
    const float* b_ih = (const float*)d_in[3];
    const float* b_hh = (const float*)d_in[4];
    const float* W1 = (const float*)d_in[5];  const float* b1 = (const float*)d_in[6];
    const float* W2 = (const float*)d_in[7];  const float* b2 = (const float*)d_in[8];
    const float* W3 = (const float*)d_in[9];  const float* b3 = (const float*)d_in[10];
    const float* W4 = (const float*)d_in[11]; const float* b4 = (const float*)d_in[12];
    const float* W5 = (const float*)d_in[13]; const float* b5 = (const float*)d_in[14];
    const float* W6 = (const float*)d_in[15]; const float* b6 = (const float*)d_in[16];
    float* out = (float*)d_out;

    float *gi, *x, *a, *b, *w1p, *w2p, *w3p, *w4p, *w5p, *w6p;
    cudaGetSymbolAddress((void**)&gi,  g_gi);
    cudaGetSymbolAddress((void**)&x,   g_x);
    cudaGetSymbolAddress((void**)&a,   g_a);
    cudaGetSymbolAddress((void**)&b,   g_b);
    cudaGetSymbolAddress((void**)&w1p, g_w1p);
    cudaGetSymbolAddress((void**)&w2p, g_w2p);
    cudaGetSymbolAddress((void**)&w3p, g_w3p);
    cudaGetSymbolAddress((void**)&w4p, g_w4p);
    cudaGetSymbolAddress((void**)&w5p, g_w5p);
    cudaGetSymbolAddress((void**)&w6p, g_w6p);

    const int prep_total = G3 * HP + DMLP * HP + 4 * DMLP * 256 + DOUT * 256;
    prep_kernel<<<(prep_total + 511) / 512, 512>>>(W_hh, W1, W2, W3, W4, W5, W6);

    // gi = history[:, 4095, :] @ W_ih^T + b_ih   (only last lane observable).
    // W_ih rows are 208 floats = 832 B: 16B-aligned, use directly (wf4 = 52).
    fc2_kernel<<<64, 512>>>(history + 4095 * FIN, TB * FIN,
                            W_ih, FIN / 4, b_ih, gi, G3, FIN / 4, G3, 0);

    // sequential GRU over 128 steps (single CTA)
    gru_kernel<<<1, 416>>>(b_hh);

    // 6-layer MLP (padded weights, pitch-256/132 activations)
    fc2_kernel<<<64, 512>>>(x, HP,  w1p, HP / 4, b1, a, 256, HP / 4, DMLP, 1);
    fc2_kernel<<<64, 512>>>(a, 256, w2p, 64,     b2, b, 256, 64,     DMLP, 1);
    fc2_kernel<<<64, 512>>>(b, 256, w3p, 64,     b3, a, 256, 64,     DMLP, 1);
    fc2_kernel<<<64, 512>>>(a, 256, w4p, 64,     b4, b, 256, 64,     DMLP, 1);
    fc2_kernel<<<64, 512>>>(b, 256, w5p, 64,     b5, a, 256, 64,     DMLP, 1);
    fc2_kernel<<<64, 512>>>(a, 256, w6p, 64,     b6, out, DOUT, 64,  DOUT, 0);
}